// round 14
// baseline (speedup 1.0000x reference)
#include <cuda_runtime.h>
#include <cuda_fp16.h>
#include <math.h>
#include <stdint.h>

#define CC    128          // channels
#define HHID  512          // expert hidden dim
#define EE    8            // routed experts
#define BB    8            // batch
#define HHW   9216         // 96*96
#define NTOK  73728        // BB*HHW
#define NOUT  (NTOK*CC)
#define TMT   128          // tokens per tile (GEMM M)
#define NE1   (EE+1)
#define W1TOT (NE1*HHID*CC)

#define LDB   272          // smem row stride in bytes (136 fp16: 128 + 8 pad)
#define TILEB (128*LDB)    // 34816 B per tile

// ---- shared memory layout (bytes); single W buffer (R10 schedule) ----
#define SM_TK    0
#define SM_TW    512
#define SM_BIAS  1024
#define SM_A     2048
#define SM_W     (SM_A+TILEB)
#define SM_H     (SM_W+TILEB)
#define SM_TOTAL (SM_H+TILEB)   // 106496 B

// ---- device scratch ----
__device__ __half g_xh[(size_t)NTOK*CC];
__device__ __half g_w1h[W1TOT];
__device__ __half g_w2h[W1TOT];
__device__ int   g_tok[EE*NTOK];
__device__ float g_wt[EE*NTOK];
__device__ int   g_cnt[EE];
__device__ float g_probsum[EE];
__device__ int   g_loadsum[EE];

// exact GELU via erff — CUDA's erff is a pure-FMA polynomial (no MUFU pressure)
__device__ __forceinline__ float gelu_exact(float v) {
    return 0.5f * v * (1.0f + erff(v * 0.70710678118654752440f));
}
__device__ __forceinline__ uint32_t smem_u32(const void* p) {
    uint32_t a;
    asm("{ .reg .u64 t; cvta.to.shared.u64 t, %1; cvt.u32.u64 %0, t; }" : "=r"(a) : "l"(p));
    return a;
}
#define CP16(s, g)   asm volatile("cp.async.cg.shared.global [%0], [%1], 16;" :: "r"(s), "l"(g) : "memory")
#define CP_COMMIT()  asm volatile("cp.async.commit_group;" ::: "memory")
#define CP_WAIT0()   asm volatile("cp.async.wait_group 0;" ::: "memory")
#define LDM_X4(r0, r1, r2, r3, a) \
    asm volatile("ldmatrix.sync.aligned.m8n8.x4.shared.b16 {%0,%1,%2,%3}, [%4];" \
        : "=r"(r0), "=r"(r1), "=r"(r2), "=r"(r3) : "r"(a))

__device__ __forceinline__ void mma16816(float* d, const uint32_t* a, const uint32_t* b) {
    asm volatile("mma.sync.aligned.m16n8k16.row.col.f32.f16.f16.f32 "
        "{%0,%1,%2,%3}, {%4,%5,%6,%7}, {%8,%9}, {%0,%1,%2,%3};"
        : "+f"(d[0]), "+f"(d[1]), "+f"(d[2]), "+f"(d[3])
        : "r"(a[0]), "r"(a[1]), "r"(a[2]), "r"(a[3]), "r"(b[0]), "r"(b[1]));
}

// one 128x128x128 GEMM chunk, single-pass fp16. Warps 4(m) x 2(n).
__device__ __forceinline__ void gemm_chunk(uint32_t aT, uint32_t wT,
                                           float acc[2][8][4], int lid, int wm, int wn) {
    int a_r  = (lid & 7) + ((lid >> 3) & 1) * 8;
    int a_ko = ((lid >> 4) & 1) * 16;
    int b_n  = (lid & 7) + ((lid >> 4) & 1) * 8;
    int b_ko = ((lid >> 3) & 1) * 16;
    uint32_t aBase = aT + (uint32_t)(wm * 32 + a_r) * LDB + a_ko;
    uint32_t bBase = wT + (uint32_t)(wn * 64 + b_n) * LDB + b_ko;

    #pragma unroll 2
    for (int k0 = 0; k0 < 8; k0++) {
        uint32_t kb = k0 * 32;
        uint32_t ah[2][4];
        #pragma unroll
        for (int mt = 0; mt < 2; mt++) {
            uint32_t ad = aBase + (uint32_t)(mt * 16) * LDB + kb;
            LDM_X4(ah[mt][0], ah[mt][1], ah[mt][2], ah[mt][3], ad);
        }
        #pragma unroll
        for (int ntp = 0; ntp < 4; ntp++) {
            uint32_t bd = bBase + (uint32_t)(ntp * 16) * LDB + kb;
            uint32_t bh[4];
            LDM_X4(bh[0], bh[1], bh[2], bh[3], bd);
            #pragma unroll
            for (int g = 0; g < 2; g++) {
                int nt = ntp * 2 + g;
                #pragma unroll
                for (int mt = 0; mt < 2; mt++)
                    mma16816(acc[mt][nt], ah[mt], bh + 2 * g);
            }
        }
    }
}

// ================================================================ transpose + fp16 convert + out=x copy + counter init
__global__ void transpose_kernel(const float* __restrict__ x, float* __restrict__ out) {
    __shared__ float t[32][33];
    int b = blockIdx.z, c0 = blockIdx.y * 32, s0 = blockIdx.x * 32;
    int tx = threadIdx.x, ty = threadIdx.y;
    if (blockIdx.x == 0 && blockIdx.y == 0 && blockIdx.z == 0 && ty == 0 && tx < EE) {
        g_cnt[tx] = 0; g_probsum[tx] = 0.f; g_loadsum[tx] = 0;
    }
    #pragma unroll
    for (int i = 0; i < 4; i++) {
        int c = c0 + ty + i * 8;
        size_t gi = (size_t)(b * CC + c) * HHW + s0 + tx;
        float v = x[gi];
        t[ty + i * 8][tx] = v;
        out[gi] = v;                    // residual init: out = x
    }
    __syncthreads();
    #pragma unroll
    for (int i = 0; i < 4; i++) {
        int s = s0 + ty + i * 8;
        g_xh[(size_t)(b * HHW + s) * CC + c0 + tx] = __float2half(t[tx][ty + i * 8]);
    }
}

// ================================================================ weight fp16 convert
__global__ void convert_w_kernel(const float* __restrict__ sw1, const float* __restrict__ ew1,
                                 const float* __restrict__ sw2, const float* __restrict__ ew2) {
    int i = blockIdx.x * 256 + threadIdx.x;
    float v1 = (i < EE * HHID * CC) ? ew1[i] : sw1[i - EE * HHID * CC];
    g_w1h[i] = __float2half(v1);
    float v2 = (i < EE * CC * HHID) ? ew2[i] : sw2[i - EE * CC * HHID];
    g_w2h[i] = __float2half(v2);
}

// ================================================================ router (4 threads/token)
__global__ void router_kernel(const float* __restrict__ x,
                              const float* __restrict__ gw,
                              const float* __restrict__ gb) {
    __shared__ float gws[EE * CC];
    __shared__ int   scnt[EE];
    __shared__ float sprob[EE];
    __shared__ int   sbase[EE];
    int tid = threadIdx.x;
    for (int i = tid; i < EE * CC; i += blockDim.x) gws[i] = gw[i];
    if (tid < EE) { scnt[tid] = 0; sprob[tid] = 0.f; }
    __syncthreads();

    int idx = blockIdx.x * 256 + tid;          // 4*NTOK threads total
    int n = idx >> 2, qu = idx & 3;
    int b = n / HHW, s = n - b * HHW;
    const float* xb = x + (size_t)b * CC * HHW + s + (size_t)(qu * 32) * HHW;
    const float* gwp = gws + qu * 32;

    float acc[EE];
    #pragma unroll
    for (int e = 0; e < EE; e++) acc[e] = qu ? 0.f : gb[e];
    #pragma unroll 8
    for (int c = 0; c < 32; c++) {
        float xv = __ldg(&xb[(size_t)c * HHW]);
        #pragma unroll
        for (int e = 0; e < EE; e++) acc[e] += xv * gwp[e * CC + c];
    }
    #pragma unroll
    for (int e = 0; e < EE; e++) {
        acc[e] += __shfl_xor_sync(0xffffffffu, acc[e], 1);
        acc[e] += __shfl_xor_sync(0xffffffffu, acc[e], 2);
    }

    bool active = (qu == 0);
    int id[3]; float pv[3]; float winv = 0.f; int slot[3];
    if (active) {
        float m = acc[0];
        #pragma unroll
        for (int e = 1; e < EE; e++) m = fmaxf(m, acc[e]);
        float sum = 0.f;
        #pragma unroll
        for (int e = 0; e < EE; e++) { acc[e] = expf(acc[e] - m); sum += acc[e]; }
        float inv = 1.f / sum;
        #pragma unroll
        for (int e = 0; e < EE; e++) { acc[e] *= inv; atomicAdd(&sprob[e], acc[e]); }
        float tmp[EE];
        #pragma unroll
        for (int e = 0; e < EE; e++) tmp[e] = acc[e];
        float wsum = 0.f;
        #pragma unroll
        for (int k = 0; k < 3; k++) {
            int bi = 0; float bv = tmp[0];
            #pragma unroll
            for (int e = 1; e < EE; e++) if (tmp[e] > bv) { bv = tmp[e]; bi = e; }
            id[k] = bi; pv[k] = bv; tmp[bi] = -1.f; wsum += bv;
        }
        winv = 1.f / wsum;
        #pragma unroll
        for (int k = 0; k < 3; k++) slot[k] = atomicAdd(&scnt[id[k]], 1);
    }
    __syncthreads();
    if (tid < EE) {
        sbase[tid] = atomicAdd(&g_cnt[tid], scnt[tid]);
        atomicAdd(&g_probsum[tid], sprob[tid]);
        atomicAdd(&g_loadsum[tid], scnt[tid]);
    }
    __syncthreads();
    if (active) {
        #pragma unroll
        for (int k = 0; k < 3; k++) {
            int pos = sbase[id[k]] + slot[k];
            g_tok[id[k] * NTOK + pos] = n;
            g_wt[id[k] * NTOK + pos]  = pv[k] * winv;
        }
    }
}

// ================================================================ aux loss
__global__ void finalize_kernel(float* __restrict__ out, int out_size) {
    if (threadIdx.x == 0) {
        float a = 0.f;
        for (int e = 0; e < EE; e++) a += g_probsum[e] * (float)g_loadsum[e];
        out[out_size - 1] = (float)EE * a / ((float)NTOK * (float)NTOK);
    }
}

// ================================================================ fused MoE (R10 schedule, erff gelu)
__global__ __launch_bounds__(256, 1) void moe_mma_kernel(
    const float* __restrict__ sb1, const float* __restrict__ sb2,
    const float* __restrict__ eb1, const float* __restrict__ eb2,
    float* __restrict__ out)
{
    extern __shared__ char sm[];
    uint32_t smb = smem_u32(sm);
    int tid = threadIdx.x, wid = tid >> 5, lid = tid & 31;
    int e = blockIdx.y;

    int count = (e < EE) ? g_cnt[e] : NTOK;
    int t0g = blockIdx.x * TMT;
    if (t0g >= count) return;

    const __half* w1h = g_w1h + (size_t)e * HHID * CC;
    const __half* w2h = g_w2h + (size_t)e * CC * HHID;
    const float* b1 = (e < EE) ? eb1 + e * HHID : sb1;
    const float* b2 = (e < EE) ? eb2 + e * CC   : sb2;

    int*   tk = (int*)(sm + SM_TK);
    float* tw = (float*)(sm + SM_TW);
    float* bs = (float*)(sm + SM_BIAS);

    if (tid < TMT) {
        int idx = t0g + tid;
        if (e < EE) {
            if (idx < count) { tk[tid] = g_tok[e * NTOK + idx]; tw[tid] = g_wt[e * NTOK + idx]; }
            else             { tk[tid] = 0;                     tw[tid] = 0.f; }
        } else { tk[tid] = idx; tw[tid] = 1.f; }
    }
    __syncthreads();

    // gather x rows into A tile via cp.async (256B per token)
    {
        int t = tid >> 1, hf = tid & 1;
        int tok = tk[t];
        const char* src = (const char*)(g_xh + (size_t)tok * CC) + hf * 128;
        uint32_t dst = smb + SM_A + t * LDB + hf * 128;
        #pragma unroll
        for (int i = 0; i < 8; i++) CP16(dst + i * 16, src + i * 16);
    }

    int wm = wid & 3, wn = wid >> 2;
    int r_lane = lid >> 2;
    int stg_n = tid & 127, stg_h = tid >> 7;   // staging: row, 128B half

    float acc2[2][8][4];
    #pragma unroll
    for (int mt = 0; mt < 2; mt++)
        #pragma unroll
        for (int nt = 0; nt < 8; nt++)
            #pragma unroll
            for (int q = 0; q < 4; q++) acc2[mt][nt][q] = 0.f;

    for (int j = 0; j < 4; j++) {
        // ---- stage w1 chunk rows [hid_out][k=C] + bias ----
        {
            const char* src = (const char*)(w1h + (size_t)(j * 128 + stg_n) * CC) + stg_h * 128;
            uint32_t dst = smb + SM_W + stg_n * LDB + stg_h * 128;
            #pragma unroll
            for (int i = 0; i < 8; i++) CP16(dst + i * 16, src + i * 16);
            if (tid < 128) bs[tid] = b1[j * 128 + tid];
        }
        CP_COMMIT(); CP_WAIT0();
        __syncthreads();

        // ---- GEMM1: [128 tok][128 hid] over K=128 ----
        float acc1[2][8][4];
        #pragma unroll
        for (int mt = 0; mt < 2; mt++)
            #pragma unroll
            for (int nt = 0; nt < 8; nt++)
                #pragma unroll
                for (int q = 0; q < 4; q++) acc1[mt][nt][q] = 0.f;
        gemm_chunk(smb + SM_A, smb + SM_W, acc1, lid, wm, wn);
        __syncthreads();   // GEMM1 reads of W done

        // ---- stage w2 chunk [128 outc][k=hid chunk]; epilogue1 -> H ----
        {
            const char* src = (const char*)(w2h + (size_t)stg_n * HHID + j * 128) + stg_h * 128;
            uint32_t dst = smb + SM_W + stg_n * LDB + stg_h * 128;
            #pragma unroll
            for (int i = 0; i < 8; i++) CP16(dst + i * 16, src + i * 16);
        }
        CP_COMMIT();
        #pragma unroll
        for (int mt = 0; mt < 2; mt++) {
            #pragma unroll
            for (int nt = 0; nt < 8; nt++) {
                int c0 = wn * 64 + nt * 8 + (lid & 3) * 2;
                float bi0 = bs[c0], bi1 = bs[c0 + 1];
                #pragma unroll
                for (int half = 0; half < 2; half++) {
                    int row = wm * 32 + mt * 16 + r_lane + half * 8;
                    float g0 = gelu_exact(acc1[mt][nt][half * 2]     + bi0);
                    float g1 = gelu_exact(acc1[mt][nt][half * 2 + 1] + bi1);
                    __half h0 = __float2half(g0), h1 = __float2half(g1);
                    uint32_t hp = ((uint32_t)__half_as_ushort(h1) << 16) | __half_as_ushort(h0);
                    *(uint32_t*)(sm + SM_H + row * LDB + c0 * 2) = hp;
                }
            }
        }
        CP_WAIT0();
        __syncthreads();

        // ---- GEMM2: [128 tok][128 outc] += H . W2^T over this 128-k chunk ----
        gemm_chunk(smb + SM_H, smb + SM_W, acc2, lid, wm, wn);
        __syncthreads();   // before next chunk overwrites W / H
    }

    // ---- final epilogue: weighted atomic scatter ----
    if (tid < 128) bs[tid] = b2[tid];
    __syncthreads();
    #pragma unroll
    for (int mt = 0; mt < 2; mt++) {
        #pragma unroll
        for (int half = 0; half < 2; half++) {
            int t = wm * 32 + mt * 16 + r_lane + half * 8;
            int tok = tk[t];
            float w = tw[t];
            int bb = tok / HHW, s = tok - bb * HHW;
            float* ob = out + (size_t)(bb * CC) * HHW + s;
            #pragma unroll
            for (int nt = 0; nt < 8; nt++) {
                int c0 = wn * 64 + nt * 8 + (lid & 3) * 2;
                atomicAdd(&ob[(size_t)c0 * HHW],
                          w * (acc2[mt][nt][half * 2]     + bs[c0]));
                atomicAdd(&ob[(size_t)(c0 + 1) * HHW],
                          w * (acc2[mt][nt][half * 2 + 1] + bs[c0 + 1]));
            }
        }
    }
}

// ================================================================
extern "C" void kernel_launch(void* const* d_in, const int* in_sizes, int n_in,
                              void* d_out, int out_size) {
    const float* x   = (const float*)d_in[0];
    const float* sw1 = (const float*)d_in[1];
    const float* sb1 = (const float*)d_in[2];
    const float* sw2 = (const float*)d_in[3];
    const float* sb2 = (const float*)d_in[4];
    const float* gw  = (const float*)d_in[5];
    const float* gb  = (const float*)d_in[6];
    const float* ew1 = (const float*)d_in[7];
    const float* eb1 = (const float*)d_in[8];
    const float* ew2 = (const float*)d_in[9];
    const float* eb2 = (const float*)d_in[10];
    float* out = (float*)d_out;

    cudaFuncSetAttribute(moe_mma_kernel,
                         cudaFuncAttributeMaxDynamicSharedMemorySize, SM_TOTAL);

    transpose_kernel<<<dim3(HHW / 32, CC / 32, BB), dim3(32, 8)>>>(x, out);
    convert_w_kernel<<<W1TOT / 256, 256>>>(sw1, ew1, sw2, ew2);
    router_kernel<<<NTOK * 4 / 256, 256>>>(x, gw, gb);
    moe_mma_kernel<<<dim3(NTOK / TMT, EE + 1), 256, SM_TOTAL>>>(sb1, sb2, eb1, eb2, out);
    finalize_kernel<<<1, 32>>>(out, out_size);
}

// round 15
// speedup vs baseline: 1.7532x; 1.7532x over previous
#include <cuda_runtime.h>
#include <cuda_fp16.h>
#include <math.h>
#include <stdint.h>

#define CC    128          // channels
#define HHID  512          // expert hidden dim
#define EE    8            // routed experts
#define BB    8            // batch
#define HHW   9216         // 96*96
#define NTOK  73728        // BB*HHW
#define TMT   128          // tokens per tile (GEMM M)
#define HC    64           // hidden chunk
#define NCH   (HHID/HC)    // 8 chunks
#define NE1   (EE+1)
#define W1TOT (NE1*HHID*CC)

#define LDA   272          // row stride bytes, K=128 tiles (A, W1 chunk)
#define LDH   144          // row stride bytes, K=64 tiles (H, W2 chunk)
#define A_SZ  34816        // 128*272
#define W_SZ  18432        // max(64*272=17408, 128*144=18432)
#define H_SZ  18432        // 128*144

// ---- shared memory layout (bytes) ----
#define SM_TK    0
#define SM_TW    512
#define SM_BIAS  1024
#define SM_A     2048
#define SM_W     (SM_A+A_SZ)      // 36864
#define SM_H     (SM_W+W_SZ)      // 55296
#define SM_TOTAL (SM_H+H_SZ)      // 73728

// ---- device scratch ----
__device__ __half g_xh[(size_t)NTOK*CC];
__device__ __half g_w1h[W1TOT];
__device__ __half g_w2h[W1TOT];
__device__ int   g_tok[EE*NTOK];
__device__ float g_wt[EE*NTOK];
__device__ int   g_cnt[EE];
__device__ float g_probsum[EE];
__device__ int   g_loadsum[EE];

// exact GELU via erff (pure-FMA polynomial in CUDA libdevice — no MUFU)
__device__ __forceinline__ float gelu_exact(float v) {
    return 0.5f * v * (1.0f + erff(v * 0.70710678118654752440f));
}
__device__ __forceinline__ uint32_t smem_u32(const void* p) {
    uint32_t a;
    asm("{ .reg .u64 t; cvta.to.shared.u64 t, %1; cvt.u32.u64 %0, t; }" : "=r"(a) : "l"(p));
    return a;
}
#define CP16(s, g)   asm volatile("cp.async.cg.shared.global [%0], [%1], 16;" :: "r"(s), "l"(g) : "memory")
#define CP_COMMIT()  asm volatile("cp.async.commit_group;" ::: "memory")
#define CP_WAIT0()   asm volatile("cp.async.wait_group 0;" ::: "memory")
#define LDM_X4(r0, r1, r2, r3, a) \
    asm volatile("ldmatrix.sync.aligned.m8n8.x4.shared.b16 {%0,%1,%2,%3}, [%4];" \
        : "=r"(r0), "=r"(r1), "=r"(r2), "=r"(r3) : "r"(a))

__device__ __forceinline__ void mma16816(float* d, const uint32_t* a, const uint32_t* b) {
    asm volatile("mma.sync.aligned.m16n8k16.row.col.f32.f16.f16.f32 "
        "{%0,%1,%2,%3}, {%4,%5,%6,%7}, {%8,%9}, {%0,%1,%2,%3};"
        : "+f"(d[0]), "+f"(d[1]), "+f"(d[2]), "+f"(d[3])
        : "r"(a[0]), "r"(a[1]), "r"(a[2]), "r"(a[3]), "r"(b[0]), "r"(b[1]));
}

// GEMM1 chunk: [128 tok] x [64 hid] over K=128. Warps 4(m)x2(n), warp tile 32x32.
__device__ __forceinline__ void gemm1(uint32_t aT, uint32_t wT, float acc[2][4][4],
                                      int lid, int wm, int wn) {
    int a_r  = (lid & 7) + ((lid >> 3) & 1) * 8;
    int a_ko = ((lid >> 4) & 1) * 16;
    int b_n  = (lid & 7) + ((lid >> 4) & 1) * 8;
    int b_ko = ((lid >> 3) & 1) * 16;
    uint32_t aBase = aT + (uint32_t)(wm * 32 + a_r) * LDA + a_ko;
    uint32_t bBase = wT + (uint32_t)(wn * 32 + b_n) * LDA + b_ko;
    #pragma unroll 2
    for (int k0 = 0; k0 < 8; k0++) {
        uint32_t kb = k0 * 32;
        uint32_t ah[2][4];
        #pragma unroll
        for (int mt = 0; mt < 2; mt++) {
            uint32_t ad = aBase + (uint32_t)(mt * 16) * LDA + kb;
            LDM_X4(ah[mt][0], ah[mt][1], ah[mt][2], ah[mt][3], ad);
        }
        #pragma unroll
        for (int ntp = 0; ntp < 2; ntp++) {
            uint32_t bd = bBase + (uint32_t)(ntp * 16) * LDA + kb;
            uint32_t bh[4];
            LDM_X4(bh[0], bh[1], bh[2], bh[3], bd);
            #pragma unroll
            for (int g = 0; g < 2; g++) {
                int nt = ntp * 2 + g;
                #pragma unroll
                for (int mt = 0; mt < 2; mt++)
                    mma16816(acc[mt][nt], ah[mt], bh + 2 * g);
            }
        }
    }
}

// GEMM2 chunk: [128 tok] x [128 outc] over K=64. Warps 4(m)x2(n), warp tile 32x64.
__device__ __forceinline__ void gemm2(uint32_t hT, uint32_t wT, float acc[2][8][4],
                                      int lid, int wm, int wn) {
    int a_r  = (lid & 7) + ((lid >> 3) & 1) * 8;
    int a_ko = ((lid >> 4) & 1) * 16;
    int b_n  = (lid & 7) + ((lid >> 4) & 1) * 8;
    int b_ko = ((lid >> 3) & 1) * 16;
    uint32_t aBase = hT + (uint32_t)(wm * 32 + a_r) * LDH + a_ko;
    uint32_t bBase = wT + (uint32_t)(wn * 64 + b_n) * LDH + b_ko;
    #pragma unroll
    for (int k0 = 0; k0 < 4; k0++) {
        uint32_t kb = k0 * 32;
        uint32_t ah[2][4];
        #pragma unroll
        for (int mt = 0; mt < 2; mt++) {
            uint32_t ad = aBase + (uint32_t)(mt * 16) * LDH + kb;
            LDM_X4(ah[mt][0], ah[mt][1], ah[mt][2], ah[mt][3], ad);
        }
        #pragma unroll
        for (int ntp = 0; ntp < 4; ntp++) {
            uint32_t bd = bBase + (uint32_t)(ntp * 16) * LDH + kb;
            uint32_t bh[4];
            LDM_X4(bh[0], bh[1], bh[2], bh[3], bd);
            #pragma unroll
            for (int g = 0; g < 2; g++) {
                int nt = ntp * 2 + g;
                #pragma unroll
                for (int mt = 0; mt < 2; mt++)
                    mma16816(acc[mt][nt], ah[mt], bh + 2 * g);
            }
        }
    }
}

// ================================================================ transpose + fp16 convert + out=x copy + counter init
__global__ void transpose_kernel(const float* __restrict__ x, float* __restrict__ out) {
    __shared__ float t[32][33];
    int b = blockIdx.z, c0 = blockIdx.y * 32, s0 = blockIdx.x * 32;
    int tx = threadIdx.x, ty = threadIdx.y;
    if (blockIdx.x == 0 && blockIdx.y == 0 && blockIdx.z == 0 && ty == 0 && tx < EE) {
        g_cnt[tx] = 0; g_probsum[tx] = 0.f; g_loadsum[tx] = 0;
    }
    #pragma unroll
    for (int i = 0; i < 4; i++) {
        int c = c0 + ty + i * 8;
        size_t gi = (size_t)(b * CC + c) * HHW + s0 + tx;
        float v = x[gi];
        t[ty + i * 8][tx] = v;
        out[gi] = v;                    // residual init: out = x
    }
    __syncthreads();
    #pragma unroll
    for (int i = 0; i < 4; i++) {
        int s = s0 + ty + i * 8;
        g_xh[(size_t)(b * HHW + s) * CC + c0 + tx] = __float2half(t[tx][ty + i * 8]);
    }
}

// ================================================================ weight fp16 convert
__global__ void convert_w_kernel(const float* __restrict__ sw1, const float* __restrict__ ew1,
                                 const float* __restrict__ sw2, const float* __restrict__ ew2) {
    int i = blockIdx.x * 256 + threadIdx.x;
    float v1 = (i < EE * HHID * CC) ? ew1[i] : sw1[i - EE * HHID * CC];
    g_w1h[i] = __float2half(v1);
    float v2 = (i < EE * CC * HHID) ? ew2[i] : sw2[i - EE * CC * HHID];
    g_w2h[i] = __float2half(v2);
}

// ================================================================ router (4 threads/token)
__global__ void router_kernel(const float* __restrict__ x,
                              const float* __restrict__ gw,
                              const float* __restrict__ gb) {
    __shared__ float gws[EE * CC];
    __shared__ int   scnt[EE];
    __shared__ float sprob[EE];
    __shared__ int   sbase[EE];
    int tid = threadIdx.x;
    for (int i = tid; i < EE * CC; i += blockDim.x) gws[i] = gw[i];
    if (tid < EE) { scnt[tid] = 0; sprob[tid] = 0.f; }
    __syncthreads();

    int idx = blockIdx.x * 256 + tid;
    int n = idx >> 2, qu = idx & 3;
    int b = n / HHW, s = n - b * HHW;
    const float* xb = x + (size_t)b * CC * HHW + s + (size_t)(qu * 32) * HHW;
    const float* gwp = gws + qu * 32;

    float acc[EE];
    #pragma unroll
    for (int e = 0; e < EE; e++) acc[e] = qu ? 0.f : gb[e];
    #pragma unroll 8
    for (int c = 0; c < 32; c++) {
        float xv = __ldg(&xb[(size_t)c * HHW]);
        #pragma unroll
        for (int e = 0; e < EE; e++) acc[e] += xv * gwp[e * CC + c];
    }
    #pragma unroll
    for (int e = 0; e < EE; e++) {
        acc[e] += __shfl_xor_sync(0xffffffffu, acc[e], 1);
        acc[e] += __shfl_xor_sync(0xffffffffu, acc[e], 2);
    }

    bool active = (qu == 0);
    int id[3]; float pv[3]; float winv = 0.f; int slot[3];
    if (active) {
        float m = acc[0];
        #pragma unroll
        for (int e = 1; e < EE; e++) m = fmaxf(m, acc[e]);
        float sum = 0.f;
        #pragma unroll
        for (int e = 0; e < EE; e++) { acc[e] = expf(acc[e] - m); sum += acc[e]; }
        float inv = 1.f / sum;
        #pragma unroll
        for (int e = 0; e < EE; e++) { acc[e] *= inv; atomicAdd(&sprob[e], acc[e]); }
        float tmp[EE];
        #pragma unroll
        for (int e = 0; e < EE; e++) tmp[e] = acc[e];
        float wsum = 0.f;
        #pragma unroll
        for (int k = 0; k < 3; k++) {
            int bi = 0; float bv = tmp[0];
            #pragma unroll
            for (int e = 1; e < EE; e++) if (tmp[e] > bv) { bv = tmp[e]; bi = e; }
            id[k] = bi; pv[k] = bv; tmp[bi] = -1.f; wsum += bv;
        }
        winv = 1.f / wsum;
        #pragma unroll
        for (int k = 0; k < 3; k++) slot[k] = atomicAdd(&scnt[id[k]], 1);
    }
    __syncthreads();
    if (tid < EE) {
        sbase[tid] = atomicAdd(&g_cnt[tid], scnt[tid]);
        atomicAdd(&g_probsum[tid], sprob[tid]);
        atomicAdd(&g_loadsum[tid], scnt[tid]);
    }
    __syncthreads();
    if (active) {
        #pragma unroll
        for (int k = 0; k < 3; k++) {
            int pos = sbase[id[k]] + slot[k];
            g_tok[id[k] * NTOK + pos] = n;
            g_wt[id[k] * NTOK + pos]  = pv[k] * winv;
        }
    }
}

// ================================================================ aux loss
__global__ void finalize_kernel(float* __restrict__ out, int out_size) {
    if (threadIdx.x == 0) {
        float a = 0.f;
        for (int e = 0; e < EE; e++) a += g_probsum[e] * (float)g_loadsum[e];
        out[out_size - 1] = (float)EE * a / ((float)NTOK * (float)NTOK);
    }
}

// ================================================================ fused MoE (HC=64, occ 2)
__global__ __launch_bounds__(256, 2) void moe_mma_kernel(
    const float* __restrict__ sb1, const float* __restrict__ sb2,
    const float* __restrict__ eb1, const float* __restrict__ eb2,
    float* __restrict__ out)
{
    extern __shared__ char sm[];
    uint32_t smb = smem_u32(sm);
    int tid = threadIdx.x, wid = tid >> 5, lid = tid & 31;
    int e = blockIdx.y;

    int count = (e < EE) ? g_cnt[e] : NTOK;
    int t0g = blockIdx.x * TMT;
    if (t0g >= count) return;

    const __half* w1h = g_w1h + (size_t)e * HHID * CC;
    const __half* w2h = g_w2h + (size_t)e * CC * HHID;
    const float* b1 = (e < EE) ? eb1 + e * HHID : sb1;
    const float* b2 = (e < EE) ? eb2 + e * CC   : sb2;

    int*   tk = (int*)(sm + SM_TK);
    float* tw = (float*)(sm + SM_TW);
    float* bs = (float*)(sm + SM_BIAS);

    if (tid < TMT) {
        int idx = t0g + tid;
        if (e < EE) {
            if (idx < count) { tk[tid] = g_tok[e * NTOK + idx]; tw[tid] = g_wt[e * NTOK + idx]; }
            else             { tk[tid] = 0;                     tw[tid] = 0.f; }
        } else { tk[tid] = idx; tw[tid] = 1.f; }
    }
    __syncthreads();

    // gather x rows into A tile via cp.async (256B per token)
    {
        int t = tid >> 1, hf = tid & 1;
        int tok = tk[t];
        const char* src = (const char*)(g_xh + (size_t)tok * CC) + hf * 128;
        uint32_t dst = smb + SM_A + t * LDA + hf * 128;
        #pragma unroll
        for (int i = 0; i < 8; i++) CP16(dst + i * 16, src + i * 16);
    }

    int wm = wid & 3, wn = wid >> 2;
    int r_lane = lid >> 2, cq = (lid & 3) * 2;
    int w1row = tid & 63, w1part = (tid >> 6) & 3;   // 64 rows x 4 x 64B
    int w2row = tid & 127, w2hf = tid >> 7;          // 128 rows x 2 x 64B

    float acc2[2][8][4];
    #pragma unroll
    for (int mt = 0; mt < 2; mt++)
        #pragma unroll
        for (int nt = 0; nt < 8; nt++)
            #pragma unroll
            for (int q = 0; q < 4; q++) acc2[mt][nt][q] = 0.f;

    for (int j = 0; j < NCH; j++) {
        // ---- stage W1 chunk [64 rows][128 k] + bias ----
        {
            const char* src = (const char*)(w1h + (size_t)(j * HC + w1row) * CC) + w1part * 64;
            uint32_t dst = smb + SM_W + w1row * LDA + w1part * 64;
            #pragma unroll
            for (int i = 0; i < 4; i++) CP16(dst + i * 16, src + i * 16);
            if (tid < HC) bs[tid] = b1[j * HC + tid];
        }
        CP_COMMIT(); CP_WAIT0();
        __syncthreads();

        // ---- GEMM1: [128 tok][64 hid] over K=128 ----
        float acc1[2][4][4];
        #pragma unroll
        for (int mt = 0; mt < 2; mt++)
            #pragma unroll
            for (int nt = 0; nt < 4; nt++)
                #pragma unroll
                for (int q = 0; q < 4; q++) acc1[mt][nt][q] = 0.f;
        gemm1(smb + SM_A, smb + SM_W, acc1, lid, wm, wn);
        __syncthreads();   // W reads done

        // ---- stage W2 chunk [128 outc][64 k]; epilogue1 -> H ----
        {
            const char* src = (const char*)(w2h + (size_t)w2row * HHID + j * HC) + w2hf * 64;
            uint32_t dst = smb + SM_W + w2row * LDH + w2hf * 64;
            #pragma unroll
            for (int i = 0; i < 4; i++) CP16(dst + i * 16, src + i * 16);
        }
        CP_COMMIT();
        #pragma unroll
        for (int mt = 0; mt < 2; mt++) {
            #pragma unroll
            for (int nt = 0; nt < 4; nt++) {
                int c0 = wn * 32 + nt * 8 + cq;
                float bi0 = bs[c0], bi1 = bs[c0 + 1];
                #pragma unroll
                for (int half = 0; half < 2; half++) {
                    int row = wm * 32 + mt * 16 + r_lane + half * 8;
                    float g0 = gelu_exact(acc1[mt][nt][half * 2]     + bi0);
                    float g1 = gelu_exact(acc1[mt][nt][half * 2 + 1] + bi1);
                    __half h0 = __float2half(g0), h1 = __float2half(g1);
                    uint32_t hp = ((uint32_t)__half_as_ushort(h1) << 16) | __half_as_ushort(h0);
                    *(uint32_t*)(sm + SM_H + row * LDH + c0 * 2) = hp;
                }
            }
        }
        CP_WAIT0();
        __syncthreads();

        // ---- GEMM2: [128 tok][128 outc] += H . W2^T over this 64-k chunk ----
        gemm2(smb + SM_H, smb + SM_W, acc2, lid, wm, wn);
        __syncthreads();   // before next chunk overwrites W / H
    }

    // ---- final epilogue: weighted atomic scatter ----
    if (tid < CC) bs[tid] = b2[tid];
    __syncthreads();
    #pragma unroll
    for (int mt = 0; mt < 2; mt++) {
        #pragma unroll
        for (int half = 0; half < 2; half++) {
            int t = wm * 32 + mt * 16 + r_lane + half * 8;
            int tok = tk[t];
            float w = tw[t];
            int bb = tok / HHW, s = tok - bb * HHW;
            float* ob = out + (size_t)(bb * CC) * HHW + s;
            #pragma unroll
            for (int nt = 0; nt < 8; nt++) {
                int c0 = wn * 64 + nt * 8 + cq;
                atomicAdd(&ob[(size_t)c0 * HHW],
                          w * (acc2[mt][nt][half * 2]     + bs[c0]));
                atomicAdd(&ob[(size_t)(c0 + 1) * HHW],
                          w * (acc2[mt][nt][half * 2 + 1] + bs[c0 + 1]));
            }
        }
    }
}

// ================================================================
extern "C" void kernel_launch(void* const* d_in, const int* in_sizes, int n_in,
                              void* d_out, int out_size) {
    const float* x   = (const float*)d_in[0];
    const float* sw1 = (const float*)d_in[1];
    const float* sb1 = (const float*)d_in[2];
    const float* sw2 = (const float*)d_in[3];
    const float* sb2 = (const float*)d_in[4];
    const float* gw  = (const float*)d_in[5];
    const float* gb  = (const float*)d_in[6];
    const float* ew1 = (const float*)d_in[7];
    const float* eb1 = (const float*)d_in[8];
    const float* ew2 = (const float*)d_in[9];
    const float* eb2 = (const float*)d_in[10];
    float* out = (float*)d_out;

    cudaFuncSetAttribute(moe_mma_kernel,
                         cudaFuncAttributeMaxDynamicSharedMemorySize, SM_TOTAL);

    transpose_kernel<<<dim3(HHW / 32, CC / 32, BB), dim3(32, 8)>>>(x, out);
    convert_w_kernel<<<W1TOT / 256, 256>>>(sw1, ew1, sw2, ew2);
    router_kernel<<<NTOK * 4 / 256, 256>>>(x, gw, gb);
    moe_mma_kernel<<<dim3(NTOK / TMT, EE + 1), 256, SM_TOTAL>>>(sb1, sb2, eb1, eb2, out);
    finalize_kernel<<<1, 32>>>(out, out_size);
}